// round 2
// baseline (speedup 1.0000x reference)
#include <cuda_runtime.h>
#include <math.h>

// Problem constants
#define NB    16
#define CC    256
#define LL    9216
#define LT    64
#define NT    144      // LL / LT
#define NHEAD 8

// ---------------------------------------------------------------------------
// Scratch (device globals -- no runtime allocation allowed)
// ---------------------------------------------------------------------------
__device__ float g_sum_part[NB * NT * CC];                 // 2.4 MB
__device__ float g_ctx_part[(size_t)NB * NT * 8192];       // 75.5 MB
__device__ float g_sumexp[NB * CC];
__device__ float g_ctx[NB * 8192];
__device__ float g_M[(size_t)NB * CC * CC];                // 4 MB

// ---------------------------------------------------------------------------
// Packed f32x2 helpers (Blackwell: 3-reg FFMA is half-rate; FFMA2 is full rate)
// ---------------------------------------------------------------------------
__device__ __forceinline__ void fma2(unsigned long long& d,
                                     unsigned long long a,
                                     unsigned long long b) {
    asm("fma.rn.f32x2 %0, %1, %2, %0;" : "+l"(d) : "l"(a), "l"(b));
}
__device__ __forceinline__ unsigned long long dup2(float a) {
    unsigned long long r;
    asm("mov.b64 %0, {%1, %1};" : "=l"(r) : "f"(a));
    return r;
}
__device__ __forceinline__ float2 unpk(unsigned long long v) {
    float2 r;
    asm("mov.b64 {%0, %1}, %2;" : "=f"(r.x), "=f"(r.y) : "l"(v));
    return r;
}

// ---------------------------------------------------------------------------
// K1: keys/values projection of context + exp + partial ctx / partial sumexp
//   grid (NT, NB), block 512
//   Computes KV = [Wk;Wv] @ c_tile (512 x 64, K=256), then
//   E = exp(K + bk), V = V + bv, partial ctx_h = E_h V_h^T, partial rowsum(E).
// ---------------------------------------------------------------------------
#define K1_AS 514   // stride of As rows (512 + pad)
#define K1_BS 66    // stride of Bs rows (64 + pad, even for 8B alignment)
#define EVS   65    // stride of Es/Vs rows (64 + pad, conflict-free columns)

__global__ __launch_bounds__(512, 1)
void k1_proj_kv(const float* __restrict__ ctx_in,
                const float* __restrict__ Wk, const float* __restrict__ bk,
                const float* __restrict__ Wv, const float* __restrict__ bv)
{
    extern __shared__ float sm[];
    float* As = sm;                    // 16 x 514
    float* Bs = As + 16 * K1_AS;       // 16 x 66
    float* Es = Bs + 16 * K1_BS;       // 256 x 65
    float* Vs = Es + 256 * EVS;        // 256 x 65

    const int tid = threadIdx.x;
    const int m_t = tid >> 3;          // 0..63
    const int n_t = tid & 7;           // 0..7
    const int t   = blockIdx.x;
    const int n   = blockIdx.y;
    const int l0  = t * LT;

    const float* wrow = (tid < CC) ? (Wk + (size_t)tid * CC)
                                   : (Wv + (size_t)(tid - CC) * CC);
    const float* cb = ctx_in + (size_t)n * CC * LL + l0;

    unsigned long long acc[8][4];
#pragma unroll
    for (int i = 0; i < 8; i++)
#pragma unroll
        for (int j = 0; j < 4; j++) acc[i][j] = 0ull;

    // software pipeline registers
    float rA[16], rB0, rB1;
    const int kk0 = tid >> 6, j0 = tid & 63;           // element 0 of B chunk
    const int kk1 = (tid + 512) >> 6, j1 = tid & 63;   // element 1 of B chunk

#pragma unroll
    for (int kk = 0; kk < 16; kk++) rA[kk] = wrow[kk];
    rB0 = cb[(size_t)kk0 * LL + j0];
    rB1 = cb[(size_t)kk1 * LL + j1];

    for (int k0 = 0; k0 < CC; k0 += 16) {
#pragma unroll
        for (int kk = 0; kk < 16; kk++) As[kk * K1_AS + tid] = rA[kk];
        Bs[kk0 * K1_BS + j0] = rB0;
        Bs[kk1 * K1_BS + j1] = rB1;
        __syncthreads();

        if (k0 + 16 < CC) {
#pragma unroll
            for (int kk = 0; kk < 16; kk++) rA[kk] = wrow[k0 + 16 + kk];
            rB0 = cb[(size_t)(k0 + 16 + kk0) * LL + j0];
            rB1 = cb[(size_t)(k0 + 16 + kk1) * LL + j1];
        }

#pragma unroll
        for (int kk = 0; kk < 16; kk++) {
            unsigned long long b[4];
            const unsigned long long* bp =
                reinterpret_cast<const unsigned long long*>(&Bs[kk * K1_BS + n_t * 8]);
#pragma unroll
            for (int jj = 0; jj < 4; jj++) b[jj] = bp[jj];
#pragma unroll
            for (int i = 0; i < 8; i++) {
                unsigned long long a2 = dup2(As[kk * K1_AS + m_t * 8 + i]);
#pragma unroll
                for (int jj = 0; jj < 4; jj++) fma2(acc[i][jj], a2, b[jj]);
            }
        }
        __syncthreads();
    }

    // Epilogue: E = exp(keys + bk), V = values + bv  -> smem
#pragma unroll
    for (int i = 0; i < 8; i++) {
        int m = m_t * 8 + i;
        if (m < CC) {
            float bias = bk[m];
            float* er = Es + m * EVS + n_t * 8;
#pragma unroll
            for (int jj = 0; jj < 4; jj++) {
                float2 v = unpk(acc[i][jj]);
                er[jj * 2]     = __expf(v.x + bias);
                er[jj * 2 + 1] = __expf(v.y + bias);
            }
        } else {
            int mv = m - CC;
            float bias = bv[mv];
            float* vr = Vs + mv * EVS + n_t * 8;
#pragma unroll
            for (int jj = 0; jj < 4; jj++) {
                float2 v = unpk(acc[i][jj]);
                vr[jj * 2]     = v.x + bias;
                vr[jj * 2 + 1] = v.y + bias;
            }
        }
    }
    __syncthreads();

    // partial sumexp per key row
    if (tid < CC) {
        const float* er = Es + tid * EVS;
        float s = 0.f;
#pragma unroll 8
        for (int l = 0; l < LT; l++) s += er[l];
        g_sum_part[(n * NT + t) * CC + tid] = s;
    }

    // partial ctx: 512 tasks, each 4k x 4v block for one head
    {
        int h   = tid >> 6;       // 0..7
        int rem = tid & 63;
        int kb  = rem >> 3;       // 0..7  -> k = kb*4 + i
        int vb  = rem & 7;        // 0..7  -> v = vb*4 + j
        const float* eb = Es + (h * 32 + kb * 4) * EVS;
        const float* vp = Vs + (h * 32 + vb * 4) * EVS;
        float a4[4][4];
#pragma unroll
        for (int i = 0; i < 4; i++)
#pragma unroll
            for (int j = 0; j < 4; j++) a4[i][j] = 0.f;

#pragma unroll 4
        for (int l = 0; l < LT; l++) {
            float e0 = eb[l], e1 = eb[EVS + l], e2 = eb[2 * EVS + l], e3 = eb[3 * EVS + l];
            float w0 = vp[l], w1 = vp[EVS + l], w2 = vp[2 * EVS + l], w3 = vp[3 * EVS + l];
            a4[0][0] += e0 * w0; a4[0][1] += e0 * w1; a4[0][2] += e0 * w2; a4[0][3] += e0 * w3;
            a4[1][0] += e1 * w0; a4[1][1] += e1 * w1; a4[1][2] += e1 * w2; a4[1][3] += e1 * w3;
            a4[2][0] += e2 * w0; a4[2][1] += e2 * w1; a4[2][2] += e2 * w2; a4[2][3] += e2 * w3;
            a4[3][0] += e3 * w0; a4[3][1] += e3 * w1; a4[3][2] += e3 * w2; a4[3][3] += e3 * w3;
        }
        float* op = g_ctx_part + (size_t)(n * NT + t) * 8192
                  + h * 1024 + (kb * 4) * 32 + vb * 4;
#pragma unroll
        for (int i = 0; i < 4; i++)
#pragma unroll
            for (int j = 0; j < 4; j++) op[i * 32 + j] = a4[i][j];
    }
}

// ---------------------------------------------------------------------------
// K2a: reduce sumexp over tiles (deterministic order)
// ---------------------------------------------------------------------------
__global__ void k2a_sum()
{
    int n = blockIdx.x, r = threadIdx.x;
    float s = 0.f;
    for (int t = 0; t < NT; t++) s += g_sum_part[(n * NT + t) * CC + r];
    g_sumexp[n * CC + r] = s;
}

// ---------------------------------------------------------------------------
// K2b: reduce ctx over tiles, normalize by sumexp of key row
// ---------------------------------------------------------------------------
__global__ void k2b_ctx()
{
    int n = blockIdx.y;
    int idx = blockIdx.x * 256 + threadIdx.x;   // 0..8191
    float s = 0.f;
    for (int t = 0; t < NT; t++)
        s += g_ctx_part[(size_t)(n * NT + t) * 8192 + idx];
    int h = idx >> 10;
    int k = (idx >> 5) & 31;
    g_ctx[n * 8192 + idx] = s / g_sumexp[n * CC + h * 32 + k];
}

// ---------------------------------------------------------------------------
// K2c: fold ctx into Wr:  M[n][o][h*32+k] = sum_v Wr[o][h*32+v] * ctx[n][h][k][v]
//   grid (NHEAD, NB), block 256
// ---------------------------------------------------------------------------
__global__ void k2c_fold(const float* __restrict__ Wr)
{
    __shared__ float ctxh[1024];
    int h = blockIdx.x, n = blockIdx.y, o = threadIdx.x;
    for (int e = threadIdx.x; e < 1024; e += 256)
        ctxh[e] = g_ctx[n * 8192 + h * 1024 + e];
    __syncthreads();

    float wr[32];
#pragma unroll
    for (int v = 0; v < 32; v++) wr[v] = Wr[(size_t)o * CC + h * 32 + v];

#pragma unroll 4
    for (int k = 0; k < 32; k++) {
        float s = 0.f;
#pragma unroll
        for (int v = 0; v < 32; v++) s += wr[v] * ctxh[k * 32 + v];
        g_M[((size_t)n * CC + o) * CC + h * 32 + k] = s;
    }
}

// ---------------------------------------------------------------------------
// K3: Q = Wq@x + bq -> per-head channel softmax -> out = M[n]@q_sm + br + x
//   grid (NT, NB), block 256
// ---------------------------------------------------------------------------
#define K3_AS 258   // 256 + pad
#define XTS   66    // x-tile stride (even)
#define QS    66    // q-tile stride (even, 8B-aligned rows)

__global__ __launch_bounds__(256, 1)
void k3_out(const float* __restrict__ x_in,
            const float* __restrict__ Wq, const float* __restrict__ bq,
            const float* __restrict__ br, float* __restrict__ out)
{
    extern __shared__ float sm[];
    float* As = sm;                   // 16 x 258
    float* XT = As + 16 * K3_AS;      // 256 x 66
    float* Q  = XT + 256 * XTS;       // 256 x 66

    const int tid = threadIdx.x;
    const int m_t = tid >> 3;         // 0..31
    const int n_t = tid & 7;          // 0..7
    const int t   = blockIdx.x;
    const int n   = blockIdx.y;
    const int l0  = t * LT;

    const float* xb = x_in + (size_t)n * CC * LL + l0;

    // load x tile (also issue first Wq chunk prefetch)
    float rA[16];
    const float* arow = Wq + (size_t)tid * CC;
#pragma unroll
    for (int kk = 0; kk < 16; kk++) rA[kk] = arow[kk];

    for (int e = tid; e < CC * LT; e += 256) {
        int ch = e >> 6, j = e & 63;
        XT[ch * XTS + j] = xb[(size_t)ch * LL + j];
    }

    unsigned long long acc[8][4];
#pragma unroll
    for (int i = 0; i < 8; i++)
#pragma unroll
        for (int j = 0; j < 4; j++) acc[i][j] = 0ull;

    // GEMM1: queries = Wq @ x_tile
    for (int k0 = 0; k0 < CC; k0 += 16) {
#pragma unroll
        for (int kk = 0; kk < 16; kk++) As[kk * K3_AS + tid] = rA[kk];
        __syncthreads();   // first iteration also fences XT loads

        if (k0 + 16 < CC) {
#pragma unroll
            for (int kk = 0; kk < 16; kk++) rA[kk] = arow[k0 + 16 + kk];
        }

#pragma unroll
        for (int kk = 0; kk < 16; kk++) {
            unsigned long long b[4];
            const unsigned long long* bp =
                reinterpret_cast<const unsigned long long*>(&XT[(k0 + kk) * XTS + n_t * 8]);
#pragma unroll
            for (int jj = 0; jj < 4; jj++) b[jj] = bp[jj];
#pragma unroll
            for (int i = 0; i < 8; i++) {
                unsigned long long a2 = dup2(As[kk * K3_AS + m_t * 8 + i]);
#pragma unroll
                for (int jj = 0; jj < 4; jj++) fma2(acc[i][jj], a2, b[jj]);
            }
        }
        __syncthreads();
    }

    // prefetch first chunk of M[n] while we do softmax
    const float* mrow = g_M + ((size_t)n * CC + tid) * CC;
#pragma unroll
    for (int kk = 0; kk < 16; kk++) rA[kk] = mrow[kk];

    // write queries (+bq) into Q
#pragma unroll
    for (int i = 0; i < 8; i++) {
        int m = m_t * 8 + i;
        float bias = bq[m];
        float* qr = Q + m * QS + n_t * 8;
#pragma unroll
        for (int jj = 0; jj < 4; jj++) {
            float2 v = unpk(acc[i][jj]);
            qr[jj * 2]     = v.x + bias;
            qr[jj * 2 + 1] = v.y + bias;
        }
    }
    __syncthreads();

    // per-(head, column) softmax over 32 channels (values tiny: no max needed)
    for (int task = tid; task < NHEAD * LT; task += 256) {
        int h = task >> 6, l = task & 63;
        float* qc = Q + (h * 32) * QS + l;
        float s = 0.f;
#pragma unroll
        for (int k = 0; k < 32; k++) {
            float w = __expf(qc[k * QS]);
            qc[k * QS] = w;
            s += w;
        }
        float inv = 1.f / s;
#pragma unroll
        for (int k = 0; k < 32; k++) qc[k * QS] *= inv;
    }
    __syncthreads();

    // GEMM2: out = M[n] @ q_sm
#pragma unroll
    for (int i = 0; i < 8; i++)
#pragma unroll
        for (int j = 0; j < 4; j++) acc[i][j] = 0ull;

    for (int k0 = 0; k0 < CC; k0 += 16) {
#pragma unroll
        for (int kk = 0; kk < 16; kk++) As[kk * K3_AS + tid] = rA[kk];
        __syncthreads();

        if (k0 + 16 < CC) {
#pragma unroll
            for (int kk = 0; kk < 16; kk++) rA[kk] = mrow[k0 + 16 + kk];
        }

#pragma unroll
        for (int kk = 0; kk < 16; kk++) {
            unsigned long long b[4];
            const unsigned long long* bp =
                reinterpret_cast<const unsigned long long*>(&Q[(k0 + kk) * QS + n_t * 8]);
#pragma unroll
            for (int jj = 0; jj < 4; jj++) b[jj] = bp[jj];
#pragma unroll
            for (int i = 0; i < 8; i++) {
                unsigned long long a2 = dup2(As[kk * K3_AS + m_t * 8 + i]);
#pragma unroll
                for (int jj = 0; jj < 4; jj++) fma2(acc[i][jj], a2, b[jj]);
            }
        }
        __syncthreads();
    }

    // Epilogue: + br + x, coalesced float2 stores
#pragma unroll
    for (int i = 0; i < 8; i++) {
        int m = m_t * 8 + i;
        float bb = br[m];
        float* op = out + ((size_t)(n * CC + m)) * LL + l0 + n_t * 8;
        const float* xr = XT + m * XTS + n_t * 8;
#pragma unroll
        for (int jj = 0; jj < 4; jj++) {
            float2 v = unpk(acc[i][jj]);
            float2 o2;
            o2.x = v.x + bb + xr[jj * 2];
            o2.y = v.y + bb + xr[jj * 2 + 1];
            reinterpret_cast<float2*>(op)[jj] = o2;
        }
    }
}

// ---------------------------------------------------------------------------
// Launch
// ---------------------------------------------------------------------------
extern "C" void kernel_launch(void* const* d_in, const int* in_sizes, int n_in,
                              void* d_out, int out_size)
{
    (void)in_sizes; (void)n_in; (void)out_size;
    const float* input_  = (const float*)d_in[0];
    const float* context = (const float*)d_in[1];
    const float* Wk = (const float*)d_in[2];
    const float* bk = (const float*)d_in[3];
    const float* Wq = (const float*)d_in[4];
    const float* bq = (const float*)d_in[5];
    const float* Wv = (const float*)d_in[6];
    const float* bv = (const float*)d_in[7];
    const float* Wr = (const float*)d_in[8];
    const float* br = (const float*)d_in[9];
    float* out = (float*)d_out;

    const size_t sm1 = (size_t)(16 * K1_AS + 16 * K1_BS + 2 * 256 * EVS) * sizeof(float); // 170240 B
    const size_t sm3 = (size_t)(16 * K3_AS + 256 * XTS + 256 * QS) * sizeof(float);       // 151680 B
    cudaFuncSetAttribute(k1_proj_kv, cudaFuncAttributeMaxDynamicSharedMemorySize, (int)sm1);
    cudaFuncSetAttribute(k3_out,     cudaFuncAttributeMaxDynamicSharedMemorySize, (int)sm3);

    k1_proj_kv<<<dim3(NT, NB), 512, sm1>>>(context, Wk, bk, Wv, bv);
    k2a_sum   <<<NB, 256>>>();
    k2b_ctx   <<<dim3(32, NB), 256>>>();
    k2c_fold  <<<dim3(NHEAD, NB), 256>>>(Wr);
    k3_out    <<<dim3(NT, NB), 256, sm3>>>(input_, Wq, bq, br, out);
}